// round 9
// baseline (speedup 1.0000x reference)
#include <cuda_runtime.h>
#include <cuda_bf16.h>
#include <cstdint>

// SequenceEmbedding: out[0][c][i][j] = one_hot(seq[i])[c]          for c in [0,4)
//                    out[0][c][i][j] = one_hot(seq[j])[c-4]        for c in [4,8)
// Output (1, 8, 4096, 4096) fp32 = 536.9 MB of pure stores.
//
// R7: emit stores via the async-proxy bulk-copy path (cp.async.bulk S2G,
// SASS UBLKCP) instead of STG through L1tex. Every output row is one of at
// most 5 distinct 16KB buffers: 4 splat rows (channels 0-3, one per base
// value) or the single pattern row (channels 4-7). Build buffers in SMEM
// once per block, then fire 64 x 16KB bulk stores.

#define SEQ_L    4096
#define NB       4
#define ROWS_PB  64          // rows per block
#define TPB      256
#define ROW_BYTES (SEQ_L * 4)        // 16384
#define SMEM_BYTES (4 * ROW_BYTES)   // 64 KB (4 splat buffers; pattern uses buf 0)

__device__ __forceinline__ bool seq_is_int64(const int* s32) {
    bool is64 = true;
#pragma unroll
    for (int k = 0; k < 64; k++) {
        if (s32[2 * k + 1] != 0) is64 = false;
    }
    return is64;
}

__device__ __forceinline__ int seq_at(const void* seq, int i, bool is64) {
    if (is64) return (int)((const long long*)seq)[i];
    return ((const int*)seq)[i];
}

__device__ __forceinline__ uint32_t smem_u32(const void* p) {
    uint32_t a;
    asm("{ .reg .u64 t; cvta.to.shared.u64 t, %1; cvt.u32.u64 %0, t; }"
        : "=r"(a) : "l"(p));
    return a;
}

__global__ void __launch_bounds__(TPB)
SequenceEmbedding_30923764532139_kernel(const void* __restrict__ seq,
                                        const float* __restrict__ bt,
                                        float* __restrict__ out) {
    extern __shared__ float4 sbuf[];     // 4 x 4096 floats = 4 x 1024 float4
    const int bx = blockIdx.x;
    const int c  = bx >> 6;              // 64 blocks per channel
    const int i0 = (bx & 63) * ROWS_PB;  // first row for this block
    const int t  = threadIdx.x;

    const bool is64 = seq_is_int64((const int*)seq);
    const int  row_f4 = SEQ_L / 4;       // 1024 float4 per 16KB row

    // ---- Build phase: fill SMEM buffers once ----
    if (c < NB) {
        // 4 splat buffers: buffer b is a full row of bt[b][c].
#pragma unroll
        for (int b = 0; b < NB; b++) {
            const float v = bt[b * NB + c];
            const float4 vv = make_float4(v, v, v, v);
#pragma unroll
            for (int k = 0; k < 4; k++) {
                sbuf[b * row_f4 + t + k * TPB] = vv;
            }
        }
    } else {
        // Pattern buffer (buf 0): pattern[j] = bt[seq[j]][c-4].
        const int cc = c - NB;
#pragma unroll
        for (int k = 0; k < 4; k++) {
            const int j = 4 * (t + k * TPB);
            float4 p;
            p.x = bt[seq_at(seq, j + 0, is64) * NB + cc];
            p.y = bt[seq_at(seq, j + 1, is64) * NB + cc];
            p.z = bt[seq_at(seq, j + 2, is64) * NB + cc];
            p.w = bt[seq_at(seq, j + 3, is64) * NB + cc];
            sbuf[t + k * TPB] = p;
        }
    }
    // Order generic SMEM writes before async-proxy reads.
    asm volatile("fence.proxy.async;" ::: "memory");
    __syncthreads();

    // ---- Emit phase: one thread fires 64 x 16KB bulk stores ----
    if (t == 0) {
        const uint32_t s_base = smem_u32(sbuf);
        char* g_base = (char*)(out + (size_t)c * SEQ_L * SEQ_L) + (size_t)i0 * ROW_BYTES;

        if (c < NB) {
            for (int r = 0; r < ROWS_PB; r++) {
                const int s = seq_at(seq, i0 + r, is64);
                const uint32_t src = s_base + (uint32_t)s * ROW_BYTES;
                asm volatile(
                    "cp.async.bulk.global.shared::cta.bulk_group [%0], [%1], %2;"
                    :: "l"(g_base + (size_t)r * ROW_BYTES), "r"(src), "r"(ROW_BYTES)
                    : "memory");
                asm volatile("cp.async.bulk.commit_group;" ::: "memory");
                asm volatile("cp.async.bulk.wait_group 8;" ::: "memory");
            }
        } else {
            for (int r = 0; r < ROWS_PB; r++) {
                asm volatile(
                    "cp.async.bulk.global.shared::cta.bulk_group [%0], [%1], %2;"
                    :: "l"(g_base + (size_t)r * ROW_BYTES), "r"(s_base), "r"(ROW_BYTES)
                    : "memory");
                asm volatile("cp.async.bulk.commit_group;" ::: "memory");
                asm volatile("cp.async.bulk.wait_group 8;" ::: "memory");
            }
        }
        asm volatile("cp.async.bulk.wait_group 0;" ::: "memory");
    }
    __syncthreads();   // keep SMEM alive until all bulk reads complete
}

extern "C" void kernel_launch(void* const* d_in, const int* in_sizes, int n_in,
                              void* d_out, int out_size) {
    const void*  seq = d_in[0];                 // 4096 ids (int32 or int64; auto-detected)
    const float* bt  = (const float*)d_in[1];   // 4x4 table, fp32
    float*       out = (float*)d_out;           // (1, 8, 4096, 4096) fp32

    cudaFuncSetAttribute(SequenceEmbedding_30923764532139_kernel,
                         cudaFuncAttributeMaxDynamicSharedMemorySize, SMEM_BYTES);

    const int grid = 8 * (SEQ_L / ROWS_PB);     // 512 blocks
    SequenceEmbedding_30923764532139_kernel<<<grid, TPB, SMEM_BYTES>>>(seq, bt, out);
}

// round 11
// speedup vs baseline: 1.2346x; 1.2346x over previous
#include <cuda_runtime.h>
#include <cuda_bf16.h>
#include <cstdint>

// SequenceEmbedding: out[0][c][i][j] = one_hot(seq[i])[c]          for c in [0,4)
//                    out[0][c][i][j] = one_hot(seq[j])[c-4]        for c in [4,8)
// Output (1, 8, 4096, 4096) fp32 = 536.9 MB of pure stores.
//
// R10 = R9 hybrid rerun (R9 died to an infra/container failure, not a kernel
// verdict). Channels 0-3 (row-splat) via deep-pipelined cp.async.bulk S2G
// (bypasses the L1tex store pipe); channels 4-7 (column pattern) via the
// proven R6 STG.128 replay path. Hardening vs R9: commit per row (64 groups)
// instead of one giant uncommitted group; single terminal wait_group 0, so
// the pipeline is still never throttled mid-flight.

#define SEQ_L     4096
#define NB        4
#define TPB       256
#define ROW_BYTES (SEQ_L * 4)       // 16384
#define CHUNK     8192              // half-row bulk copy
#define SMEM_BYTES (NB * CHUNK)     // 32 KB: 4 uniform splat buffers

#define TMA_BLKS_PER_CH 64          // 64 rows per TMA block
#define TMA_ROWS_PB     64
#define STG_BLKS_PER_CH 512         // 8 rows per STG block
#define STG_ROWS_PB     8
#define N_TMA_BLKS (NB * TMA_BLKS_PER_CH)   // 256
#define N_STG_BLKS (NB * STG_BLKS_PER_CH)   // 2048

__device__ __forceinline__ bool seq_is_int64(const int* s32) {
    bool is64 = true;
#pragma unroll
    for (int k = 0; k < 64; k++) {
        if (s32[2 * k + 1] != 0) is64 = false;
    }
    return is64;
}

__device__ __forceinline__ int seq_at(const void* seq, int i, bool is64) {
    if (is64) return (int)((const long long*)seq)[i];
    return ((const int*)seq)[i];
}

__device__ __forceinline__ uint32_t smem_u32(const void* p) {
    uint32_t a;
    asm("{ .reg .u64 t; cvta.to.shared.u64 t, %1; cvt.u32.u64 %0, t; }"
        : "=r"(a) : "l"(p));
    return a;
}

__global__ void __launch_bounds__(TPB)
SequenceEmbedding_30923764532139_kernel(const void* __restrict__ seq,
                                        const float* __restrict__ bt,
                                        float* __restrict__ out) {
    extern __shared__ float4 sbuf[];     // 4 x 8KB (TMA blocks only)
    const int bx = blockIdx.x;
    const int t  = threadIdx.x;
    const bool is64 = seq_is_int64((const int*)seq);

    if (bx < N_TMA_BLKS) {
        // ---------- Bulk-copy path: splat channels 0-3 ----------
        const int c  = bx >> 6;                      // 0..3
        const int i0 = (bx & (TMA_BLKS_PER_CH - 1)) * TMA_ROWS_PB;
        const int buf_f4 = CHUNK / 16;               // 512 float4 per buffer

        // Fill 4 uniform buffers: buffer b = splat of bt[b][c].
#pragma unroll
        for (int b = 0; b < NB; b++) {
            const float v = bt[b * NB + c];
            const float4 vv = make_float4(v, v, v, v);
#pragma unroll
            for (int k = 0; k < 2; k++) {
                sbuf[b * buf_f4 + t + k * TPB] = vv;
            }
        }
        asm volatile("fence.proxy.async;" ::: "memory");
        __syncthreads();

        if (t == 0) {
            const uint32_t s_base = smem_u32(sbuf);
            char* g_base = (char*)(out + (size_t)c * SEQ_L * SEQ_L)
                         + (size_t)i0 * ROW_BYTES;
            // Deep pipeline: issue all copies; commit per row; no mid-flight
            // wait (single wait_group 0 at the end).
            for (int r = 0; r < TMA_ROWS_PB; r++) {
                const int s = seq_at(seq, i0 + r, is64);
                const uint32_t src = s_base + (uint32_t)s * CHUNK;
                char* dst = g_base + (size_t)r * ROW_BYTES;
                asm volatile(
                    "cp.async.bulk.global.shared::cta.bulk_group [%0], [%1], %2;"
                    :: "l"(dst), "r"(src), "n"(CHUNK) : "memory");
                asm volatile(
                    "cp.async.bulk.global.shared::cta.bulk_group [%0], [%1], %2;"
                    :: "l"(dst + CHUNK), "r"(src), "n"(CHUNK) : "memory");
                asm volatile("cp.async.bulk.commit_group;" ::: "memory");
            }
            asm volatile("cp.async.bulk.wait_group 0;" ::: "memory");
        }
        __syncthreads();   // SMEM must outlive the bulk reads
    } else {
        // ---------- STG path: pattern channels 4-7 (R6-proven) ----------
        const int sb = bx - N_TMA_BLKS;
        const int cc = sb >> 9;                      // 0..3 -> out channel 4+cc
        const int i0 = (sb & (STG_BLKS_PER_CH - 1)) * STG_ROWS_PB;
        const int row_f4 = SEQ_L / 4;

        float4* __restrict__ chan =
            (float4*)(out + (size_t)(NB + cc) * SEQ_L * SEQ_L);

        float4 p[4];
#pragma unroll
        for (int k = 0; k < 4; k++) {
            const int j = 4 * (t + k * TPB);
            p[k].x = bt[seq_at(seq, j + 0, is64) * NB + cc];
            p[k].y = bt[seq_at(seq, j + 1, is64) * NB + cc];
            p[k].z = bt[seq_at(seq, j + 2, is64) * NB + cc];
            p[k].w = bt[seq_at(seq, j + 3, is64) * NB + cc];
        }
#pragma unroll
        for (int r = 0; r < STG_ROWS_PB; r++) {
            float4* rowp = chan + (size_t)(i0 + r) * row_f4;
#pragma unroll
            for (int k = 0; k < 4; k++) {
                rowp[t + k * TPB] = p[k];
            }
        }
    }
}

extern "C" void kernel_launch(void* const* d_in, const int* in_sizes, int n_in,
                              void* d_out, int out_size) {
    const void*  seq = d_in[0];                 // 4096 ids (int32 or int64; auto-detected)
    const float* bt  = (const float*)d_in[1];   // 4x4 table, fp32
    float*       out = (float*)d_out;           // (1, 8, 4096, 4096) fp32

    cudaFuncSetAttribute(SequenceEmbedding_30923764532139_kernel,
                         cudaFuncAttributeMaxDynamicSharedMemorySize, SMEM_BYTES);

    const int grid = N_TMA_BLKS + N_STG_BLKS;   // 2304 blocks
    SequenceEmbedding_30923764532139_kernel<<<grid, TPB, SMEM_BYTES>>>(seq, bt, out);
}